// round 9
// baseline (speedup 1.0000x reference)
#include <cuda_runtime.h>

// NCN recurrence, decomposed by (batch, head).
// R7 diagnosis: L1/shared datapath at 81.7% (16 LDS.128 broadcasts per warp-step)
// is the binder; fma only 43%. R8 fix (this kernel, resubmitted after a static
// smem overflow: shW+ring was 53KB > 48KB; now the weight staging area ALIASES
// the ring -- W is only live in smem between stage and register-gather, before
// the ring is primed each module):
//  * k-split: lanes 0-15 read k[0:32), lanes 16-31 read k[32:64) -> 8 LDS.128
//    per step. Each lane covers 2 channels; combine via 2 scalar shfl.bfly(16).
//  * CONFLICT-FREE split staging: each step buffer = 72 floats, k-half1 at
//    +144B so the two half-warp addresses of one LDS.128 land in disjoint
//    bank groups -> one wavefront, no replay.
//  * R6's 4-step groups / 8-deep ring / one __syncwarp per 4 steps.
//  * weights: 2 ch x 16 k-pairs = 32 u64 = 64 regs/thread, no spill.
//  * tanh(u/2) = 1 - 2/(e^u+1) via ex2.approx + rcp.approx.
//  * ping-pong: one 128MB __device__ static + the x-section of d_out.

#define NB 8
#define NT 4096
#define ND 1024
#define NH 16
#define DH 64
#define NC 8
#define NSTEPS (NT / NC)   // 512
#define NMOD 4
#define BTD (NB * NT * ND) // 33554432

#define BUF_F 72           // floats per step buffer (2 x 32 data + padding)
#define HALF_OFF 36        // float offset of k-half 1 (= 144 bytes)
#define RING_F (8 * BUF_F) // 576 floats per warp ring

__device__ float g_buf[BTD];

typedef unsigned long long u64;

__device__ __forceinline__ u64 ffma2(u64 a, u64 b, u64 c) {
    u64 d;
    asm("fma.rn.f32x2 %0, %1, %2, %3;" : "=l"(d) : "l"(a), "l"(b), "l"(c));
    return d;
}
__device__ __forceinline__ u64 fadd2(u64 a, u64 b) {
    u64 d;
    asm("add.rn.f32x2 %0, %1, %2;" : "=l"(d) : "l"(a), "l"(b));
    return d;
}
__device__ __forceinline__ u64 packf2(float lo, float hi) {
    u64 d;
    asm("mov.b64 %0, {%1, %2};" : "=l"(d) : "f"(lo), "f"(hi));
    return d;
}
__device__ __forceinline__ float2 unpackf2(u64 v) {
    float lo, hi;
    asm("mov.b64 {%0, %1}, %2;" : "=f"(lo), "=f"(hi) : "l"(v));
    return make_float2(lo, hi);
}
__device__ __forceinline__ float shfl_bfly16(float v) {
    float r;
    asm("shfl.sync.bfly.b32 %0, %1, 16, 0x1F, 0xFFFFFFFF;" : "=f"(r) : "f"(v));
    return r;
}

// tanh(0.5f*u) = 1 - 2/(e^u + 1); ~1e-6 abs error.
__device__ __forceinline__ float tanh_half(float u) {
    float e;
    asm("ex2.approx.f32 %0, %1;" : "=f"(e) : "f"(u * 1.4426950408889634f));
    float r;
    asm("rcp.approx.f32 %0, %1;" : "=f"(r) : "f"(e + 1.0f));
    return fmaf(-2.0f, r, 1.0f);
}

__global__ void __launch_bounds__(512, 1)
ncn_kernel(const float* __restrict__ x_in,
           const float* __restrict__ xa_in,
           const float* __restrict__ w_in,
           float* __restrict__ out_x,
           float* __restrict__ out_xa)
{
    // Single 36 KB shared array. Per module, its first 4096 floats briefly
    // stage W[m][h] (before the ring is primed); afterwards the whole array
    // is the 16-warp x ring.
    __shared__ float sh[16 * RING_F];
    float* shW = sh;

    const int b    = blockIdx.x >> 4;          // grid = 128 = B * H
    const int h    = blockIdx.x & 15;
    const int warp = threadIdx.x >> 5;
    const int lane = threadIdx.x & 31;
    const int s    = warp & 7;                 // cache slot (this warp's chain)
    const int hf   = warp >> 3;                // channel half
    const int kl   = lane >> 4;                // k-split: 0 -> k[0:32), 1 -> k[32:64)
    const int j    = lane & 15;
    const int e0   = hf * 32 + 2 * j;          // this lane's channels e0, e0+1

    float* ring = &sh[warp * RING_F];

    // Staging offset for lane's float2 (channels 2*lane, 2*lane+1): lanes 0-15
    // write floats [2l, 2l+1], lanes 16-31 write [HALF_OFF + 2(l-16), ...].
    const int stoff = (lane < 16) ? (2 * lane) : (HALF_OFF + 2 * (lane - 16));

    // Cache for channels e0,e0+1 of slot s; both kl-partners keep a copy.
    float2 c2 = *(const float2*)(xa_in + (size_t)(b * NC + s) * ND + h * DH + e0);

    // Weights for this lane's k-range, 2 channels: 32 u64 = 64 regs.
    // wA[i] = (W[2kp][e0],   W[2kp+1][e0]),   kp = kl*16 + i
    // wB[i] = (W[2kp][e0+1], W[2kp+1][e0+1])
    u64 wA[16], wB[16];

    #pragma unroll 1
    for (int m = 0; m < NMOD; ++m) {
        // Ping-pong: x_in -> g_buf -> out_x -> g_buf -> out_x
        const float* src = (m == 0) ? x_in  : (m & 1) ? g_buf : out_x;
        float*       dst = (m & 1) ? out_x : g_buf;

        // --- stage W[m][h] into the (currently idle) ring area, gather ---
        __syncthreads();  // all warps done reading the previous ring contents
        const float* wg = w_in + (size_t)(m * NH + h) * DH * DH;
        for (int i = threadIdx.x; i < DH * DH; i += 512) shW[i] = wg[i];
        __syncthreads();
        #pragma unroll
        for (int i = 0; i < 16; ++i) {
            int k0 = (kl * 16 + i) * 2;
            wA[i] = packf2(shW[k0 * DH + e0],     shW[(k0 + 1) * DH + e0]);
            wB[i] = packf2(shW[k0 * DH + e0 + 1], shW[(k0 + 1) * DH + e0 + 1]);
        }
        __syncthreads();  // gather reads done before ring priming overwrites shW

        const size_t base   = (size_t)b * NT * ND + (size_t)s * ND + h * DH;
        const size_t stride = (size_t)NC * ND;     // next step of this slot chain
        const float* xp  = src + base + 2 * lane;  // staging: lane loads ch 2l,2l+1
        float*       ypc = dst + base + e0;        // output cursor (kl==0 writes)

        // ---- prime: stage x(0..3) into bufs 0..3 (padded), prefetch x(4..7) ----
        {
            float2 r0 = *(const float2*)(xp);
            float2 r1 = *(const float2*)(xp + stride);
            float2 r2 = *(const float2*)(xp + 2 * stride);
            float2 r3 = *(const float2*)(xp + 3 * stride);
            *(float2*)(ring + 0 * BUF_F + stoff) = r0;
            *(float2*)(ring + 1 * BUF_F + stoff) = r1;
            *(float2*)(ring + 2 * BUF_F + stoff) = r2;
            *(float2*)(ring + 3 * BUF_F + stoff) = r3;
        }
        float2 px0 = *(const float2*)(xp + 4 * stride);
        float2 px1 = *(const float2*)(xp + 5 * stride);
        float2 px2 = *(const float2*)(xp + 6 * stride);
        float2 px3 = *(const float2*)(xp + 7 * stride);
        const float* xpf = xp + 8 * stride;   // LDG cursor: x(p+8) at group p

        // ---- main loop: groups of 4 steps ----
        #pragma unroll 1
        for (int p = 0; p < NSTEPS; p += 4) {
            const int g = (p >> 2) & 1;
            const float* rb = ring + (4 * g) * BUF_F;        // bufs for x p..p+3
            float*       wb = ring + (4 * (1 - g)) * BUF_F;  // bufs to refill

            __syncwarp();   // prior group's reads of wb done; prior STS visible

            #pragma unroll
            for (int q = 0; q < 4; ++q) {
                // This lane's k-half of step q's x: 8 conflict-free LDS.128
                // (lower half-warp at +0, upper at +144B -> disjoint banks).
                const ulonglong2* xs =
                    (const ulonglong2*)(rb + q * BUF_F + kl * HALF_OFF);
                u64 a0 = 0, a1 = 0, a2 = 0, a3 = 0;
                #pragma unroll
                for (int i = 0; i < 8; ++i) {
                    ulonglong2 xv = xs[i];
                    a0 = ffma2(xv.x, wA[2 * i],     a0);
                    a1 = ffma2(xv.y, wA[2 * i + 1], a1);
                    a2 = ffma2(xv.x, wB[2 * i],     a2);
                    a3 = ffma2(xv.y, wB[2 * i + 1], a3);
                }
                float2 f0 = unpackf2(fadd2(a0, a1));  // channel e0 partials
                float2 f1 = unpackf2(fadd2(a2, a3));  // channel e0+1 partials
                float s0 = f0.x + f0.y;
                float s1 = f1.x + f1.y;
                // combine k-halves across the bfly(16) partner
                float mix0 = s0 + shfl_bfly16(s0);
                float mix1 = s1 + shfl_bfly16(s1);
                c2.x = tanh_half(c2.x + mix0);
                c2.y = tanh_half(c2.y + mix1);
                if (kl == 0) *(float2*)(ypc + (size_t)q * stride) = c2;
            }
            ypc += 4 * stride;

            // stage x(p+4..p+7) into the other 4 buffers (padded layout)
            *(float2*)(wb + 0 * BUF_F + stoff) = px0;
            *(float2*)(wb + 1 * BUF_F + stoff) = px1;
            *(float2*)(wb + 2 * BUF_F + stoff) = px2;
            *(float2*)(wb + 3 * BUF_F + stoff) = px3;

            // refill prefetch regs with x(p+8..p+11)
            if (p + 8 < NSTEPS) {
                px0 = *(const float2*)(xpf);
                px1 = *(const float2*)(xpf + stride);
                px2 = *(const float2*)(xpf + 2 * stride);
                px3 = *(const float2*)(xpf + 3 * stride);
            }
            xpf += 4 * stride;
        }
    }

    // Final cache for slot s == its last y value (in c2); kl==0 lanes write.
    if (kl == 0)
        *(float2*)(out_xa + (size_t)(b * NC + s) * ND + h * DH + e0) = c2;
}

extern "C" void kernel_launch(void* const* d_in, const int* in_sizes, int n_in,
                              void* d_out, int out_size) {
    const float* x  = (const float*)d_in[0];   // [8, 4096, 1024] fp32
    const float* xa = (const float*)d_in[1];   // [8, 8, 1024]    fp32
    const float* w  = (const float*)d_in[2];   // [4, 16, 64, 64] fp32

    float* out_x  = (float*)d_out;                              // x part
    float* out_xa = (float*)d_out + (out_size - NB * NC * ND);  // xa part (last 65536)

    ncn_kernel<<<NB * NH, 512>>>(x, xa, w, out_x, out_xa);
}

// round 10
// speedup vs baseline: 1.0917x; 1.0917x over previous
#include <cuda_runtime.h>

// NCN recurrence, decomposed by (batch, head).
// R9 post-mortem: k-split halved LDS (L1 82->39%) but its shfl/combine pushed
// alu to 49.6% and regressed (858us vs R7's 663us). This version gets the same
// LDS halving with NO cross-lane tax: 2 channels/thread, full-k, 8 warps.
//  * 8 warps x 256 threads: warp = cache slot; each thread owns channels
//    (2*lane, 2*lane+1). x is staged/read ONCE per slot-step (R7's two
//    half-channel warps read it twice) -> LDS wavefronts halve: 0.52M/SM,
//    balancing the 0.52M-cycle FMA floor on a different pipe.
//  * weights: 64 x u64 (f32x2 k-pairs for 2 channels) = 128 regs; legal and
//    unspilled at 256 threads/block (255-reg cap; R2's "spill" diagnosis was
//    wrong -- its L1 traffic was LDS broadcasts, its stall was per-step sync).
//  * R6's 4-step groups / 8-deep per-warp ring / one __syncwarp per 4 steps.
//  * 4 accumulators; cache c only enters at the tanh tail (cross-step ILP).
//  * tanh(u/2) = 1 - 2/(e^u+1) via ex2.approx + rcp.approx.
//  * ping-pong: one 128MB __device__ static + the x-section of d_out.

#define NB 8
#define NT 4096
#define ND 1024
#define NH 16
#define DH 64
#define NC 8
#define NSTEPS (NT / NC)   // 512
#define NMOD 4
#define BTD (NB * NT * ND) // 33554432

__device__ float g_buf[BTD];

typedef unsigned long long u64;

__device__ __forceinline__ u64 ffma2(u64 a, u64 b, u64 c) {
    u64 d;
    asm("fma.rn.f32x2 %0, %1, %2, %3;" : "=l"(d) : "l"(a), "l"(b), "l"(c));
    return d;
}
__device__ __forceinline__ u64 fadd2(u64 a, u64 b) {
    u64 d;
    asm("add.rn.f32x2 %0, %1, %2;" : "=l"(d) : "l"(a), "l"(b));
    return d;
}
__device__ __forceinline__ u64 packf2(float lo, float hi) {
    u64 d;
    asm("mov.b64 %0, {%1, %2};" : "=l"(d) : "f"(lo), "f"(hi));
    return d;
}
__device__ __forceinline__ float2 unpackf2(u64 v) {
    float lo, hi;
    asm("mov.b64 {%0, %1}, %2;" : "=f"(lo), "=f"(hi) : "l"(v));
    return make_float2(lo, hi);
}

// tanh(0.5f*u) = 1 - 2/(e^u + 1); ~1e-6 abs error.
__device__ __forceinline__ float tanh_half(float u) {
    float e;
    asm("ex2.approx.f32 %0, %1;" : "=f"(e) : "f"(u * 1.4426950408889634f));
    float r;
    asm("rcp.approx.f32 %0, %1;" : "=f"(r) : "f"(e + 1.0f));
    return fmaf(-2.0f, r, 1.0f);
}

__global__ void __launch_bounds__(256, 1)
ncn_kernel(const float* __restrict__ x_in,
           const float* __restrict__ xa_in,
           const float* __restrict__ w_in,
           float* __restrict__ out_x,
           float* __restrict__ out_xa)
{
    __shared__ float shW[DH * DH];     // 16 KB weight staging
    __shared__ float shx[8][8][DH];    // 16 KB: per-warp 8-deep x ring

    const int b    = blockIdx.x >> 4;  // grid = 128 = B * H
    const int h    = blockIdx.x & 15;
    const int warp = threadIdx.x >> 5; // warp == cache slot s (8 warps)
    const int lane = threadIdx.x & 31;
    const int s    = warp;
    const int e0   = 2 * lane;         // this thread's channels e0, e0+1

    // Cache for channels e0,e0+1 of slot s; persists across modules.
    float2 c2 = *(const float2*)(xa_in + (size_t)(b * NC + s) * ND + h * DH + e0);

    // Per-thread weights (2 channels x 32 k-pairs): 64 u64 = 128 regs.
    // wA[kp] = (W[2kp][e0],   W[2kp+1][e0])
    // wB[kp] = (W[2kp][e0+1], W[2kp+1][e0+1])
    u64 wA[32], wB[32];

    #pragma unroll 1
    for (int m = 0; m < NMOD; ++m) {
        // Ping-pong: x_in -> g_buf -> out_x -> g_buf -> out_x
        const float* src = (m == 0) ? x_in  : (m & 1) ? g_buf : out_x;
        float*       dst = (m & 1) ? out_x : g_buf;

        __syncthreads();
        const float* wg = w_in + (size_t)(m * NH + h) * DH * DH;
        for (int i = threadIdx.x; i < DH * DH; i += 256) shW[i] = wg[i];
        __syncthreads();
        #pragma unroll
        for (int kp = 0; kp < 32; ++kp) {
            wA[kp] = packf2(shW[(2 * kp) * DH + e0],     shW[(2 * kp + 1) * DH + e0]);
            wB[kp] = packf2(shW[(2 * kp) * DH + e0 + 1], shW[(2 * kp + 1) * DH + e0 + 1]);
        }

        const size_t base   = (size_t)b * NT * ND + (size_t)s * ND + h * DH;
        const size_t stride = (size_t)NC * ND;     // next step of this slot chain
        const float* xp  = src + base + e0;        // staging == compute channels
        float*       ypc = dst + base + e0;        // output cursor (float2 store)

        // ---- prime: stage x(0..3) into bufs 0..3, prefetch x(4..7) ----
        {
            float2 r0 = *(const float2*)(xp);
            float2 r1 = *(const float2*)(xp + stride);
            float2 r2 = *(const float2*)(xp + 2 * stride);
            float2 r3 = *(const float2*)(xp + 3 * stride);
            *(float2*)&shx[warp][0][e0] = r0;
            *(float2*)&shx[warp][1][e0] = r1;
            *(float2*)&shx[warp][2][e0] = r2;
            *(float2*)&shx[warp][3][e0] = r3;
        }
        float2 px0 = *(const float2*)(xp + 4 * stride);
        float2 px1 = *(const float2*)(xp + 5 * stride);
        float2 px2 = *(const float2*)(xp + 6 * stride);
        float2 px3 = *(const float2*)(xp + 7 * stride);
        const float* xpf = xp + 8 * stride;   // LDG cursor: x(p+8) at group p

        // ---- main loop: groups of 4 steps ----
        #pragma unroll 1
        for (int p = 0; p < NSTEPS; p += 4) {
            const int g = (p >> 2) & 1;
            const float* rb = &shx[warp][4 * g][0];        // bufs for x p..p+3
            float*       wb = &shx[warp][4 * (1 - g)][0];  // bufs to refill

            __syncwarp();   // prior group's reads of wb done; prior STS visible

            #pragma unroll
            for (int q = 0; q < 4; ++q) {
                const ulonglong2* xs = (const ulonglong2*)(rb + q * DH);
                u64 a0 = 0, a1 = 0, a2 = 0, a3 = 0;
                #pragma unroll
                for (int i = 0; i < 16; ++i) {
                    ulonglong2 xv = xs[i];   // broadcast: x[4i..4i+3]
                    a0 = ffma2(xv.x, wA[2 * i],     a0);
                    a1 = ffma2(xv.y, wA[2 * i + 1], a1);
                    a2 = ffma2(xv.x, wB[2 * i],     a2);
                    a3 = ffma2(xv.y, wB[2 * i + 1], a3);
                }
                float2 f0 = unpackf2(fadd2(a0, a1));  // channel e0
                float2 f1 = unpackf2(fadd2(a2, a3));  // channel e0+1
                // serial part: only this depends on the previous step's c
                c2.x = tanh_half(c2.x + f0.x + f0.y);
                c2.y = tanh_half(c2.y + f1.x + f1.y);
                *(float2*)(ypc + (size_t)q * stride) = c2;
            }
            ypc += 4 * stride;

            // stage x(p+4..p+7) into the other 4 buffers
            *(float2*)(wb + 0 * DH + e0) = px0;
            *(float2*)(wb + 1 * DH + e0) = px1;
            *(float2*)(wb + 2 * DH + e0) = px2;
            *(float2*)(wb + 3 * DH + e0) = px3;

            // refill prefetch regs with x(p+8..p+11)
            if (p + 8 < NSTEPS) {
                px0 = *(const float2*)(xpf);
                px1 = *(const float2*)(xpf + stride);
                px2 = *(const float2*)(xpf + 2 * stride);
                px3 = *(const float2*)(xpf + 3 * stride);
            }
            xpf += 4 * stride;
        }
    }

    // Final cache for slot s == its last y value (still in c2).
    *(float2*)(out_xa + (size_t)(b * NC + s) * ND + h * DH + e0) = c2;
}

extern "C" void kernel_launch(void* const* d_in, const int* in_sizes, int n_in,
                              void* d_out, int out_size) {
    const float* x  = (const float*)d_in[0];   // [8, 4096, 1024] fp32
    const float* xa = (const float*)d_in[1];   // [8, 8, 1024]    fp32
    const float* w  = (const float*)d_in[2];   // [4, 16, 64, 64] fp32

    float* out_x  = (float*)d_out;                              // x part
    float* out_xa = (float*)d_out + (out_size - NB * NC * ND);  // xa part (last 65536)

    ncn_kernel<<<NB * NH, 256>>>(x, xa, w, out_x, out_xa);
}